// round 15
// baseline (speedup 1.0000x reference)
#include <cuda_runtime.h>
#include <cuda_bf16.h>
#include <math.h>
#include <stdint.h>

#define NQ   2197
#define NQP  2200           /* padded scores row stride (16B-aligned rows) */
#define CDIM 216
#define KEYD 512
#define HCNT 8
#define HD   64
#define NHD  (NQ*HD)        /* 140608 */
#define FXD  338
#define FX2  114244         /* 338*338 */
#define LD   42
#define X4TOT 38614472      /* 338^3 == 8*2197^2 */
#define OUT3 74088          /* 42^3 */
#define KSPLIT 192          /* K:[hi|hi|lo]  Q:[hi|lo|hi] -> hh + h*lo + lo*h */
#define KC3  64             /* cp.async K-chunk (3 chunks) */
#define SPAD3 72            /* smem row stride (bf16) for 64-wide chunk */
#define WPAD 44             /* padded i-dim for transposed weights */
#define BHALF 169           /* tcl2 b-split */
#define NSLICE 16           /* bn_stats stage-1 slices */

/* ---------------- packed fp32x2 helpers (Blackwell FFMA2 path) ------------------ */
#define FFMA2(d, a, b) asm("fma.rn.f32x2 %0, %1, %2, %0;" : "+l"(d) : "l"(a), "l"(b))
__device__ __forceinline__ unsigned long long dup2(float x) {
    unsigned long long r;
    asm("mov.b64 %0, {%1, %1};" : "=l"(r) : "f"(x));
    return r;
}
__device__ __forceinline__ float2 unpk2(unsigned long long d) {
    float2 f;
    asm("mov.b64 {%0, %1}, %2;" : "=f"(f.x), "=f"(f.y) : "l"(d));
    return f;
}
#define CP_ASYNC16(dst, src, sz) \
    asm volatile("cp.async.cg.shared.global [%0], [%1], 16, %2;" :: "r"(dst), "l"(src), "r"(sz))
#define CP_COMMIT() asm volatile("cp.async.commit_group;" ::: "memory")
#define CP_WAIT(n)  asm volatile("cp.async.wait_group %0;" :: "n"(n) : "memory")

/* ---------------- static device scratch (no runtime allocation) ---------------- */
__device__ float g_q[NQ*KEYD];
__device__ float g_k[NQ*KEYD];
__device__ __nv_bfloat16 g_Qs[(long)HCNT*NQ*KSPLIT];
__device__ __nv_bfloat16 g_Ks[(long)HCNT*NQ*KSPLIT];
__device__ double g_part[2*HCNT*NSLICE*2];
__device__ float g_scores[(long)HCNT*NQ*NQP]; /* scoresT[h][m][q], stride NQP */
__device__ float g_tau[HCNT*NQ];
__device__ float g_att[(long)X4TOT];          /* fallback att(t,m) dest */
__device__ float g_out1[(long)LD*FX2];
__device__ float g_out2[2][LD*LD*FXD];

/* ------- fp32 projection GEMM: 64x64 tile, 4x4/thread, f32x2 FMA, K=216 -------- */
__global__ void proj_gemm_k(const float* __restrict__ A,
                            const float* __restrict__ B0, const float* __restrict__ B1,
                            float* __restrict__ C0, float* __restrict__ C1)
{
    const float* __restrict__ B = blockIdx.z ? B1 : B0;
    float* __restrict__ C = blockIdx.z ? C1 : C0;
    const int M = NQ, N = KEYD, K = CDIM;

    __shared__ float As[32][65];
    __shared__ __align__(16) float Bs[32][68];

    int tid = threadIdx.x;
    int tx = tid & 15, ty = tid >> 4;
    int m0 = blockIdx.x * 64, n0 = blockIdx.y * 64;
    unsigned long long acc2[4][2];
#pragma unroll
    for (int i = 0; i < 4; i++) { acc2[i][0] = 0ull; acc2[i][1] = 0ull; }

    for (int k0 = 0; k0 < K; k0 += 32) {
#pragma unroll
        for (int l = 0; l < 2; l++) {
            int s = tid + l * 256;
            int row = s >> 3, kq = s & 7;
            bool kok = (k0 + kq*4) < K;
            int mm = m0 + row;
            float4 va = make_float4(0.f,0.f,0.f,0.f);
            if (mm < M && kok) va = *(const float4*)&A[(long)mm * K + k0 + kq*4];
            As[kq*4+0][row] = va.x; As[kq*4+1][row] = va.y;
            As[kq*4+2][row] = va.z; As[kq*4+3][row] = va.w;
            int nn = n0 + row;
            float4 vb = make_float4(0.f,0.f,0.f,0.f);
            if (kok) vb = *(const float4*)&B[(long)nn * K + k0 + kq*4];
            Bs[kq*4+0][row] = vb.x; Bs[kq*4+1][row] = vb.y;
            Bs[kq*4+2][row] = vb.z; Bs[kq*4+3][row] = vb.w;
        }
        __syncthreads();
#pragma unroll
        for (int k = 0; k < 32; k++) {
            ulonglong2 bp = *(const ulonglong2*)&Bs[k][tx*4];
#pragma unroll
            for (int i = 0; i < 4; i++) {
                unsigned long long av = dup2(As[k][ty*4+i]);
                FFMA2(acc2[i][0], av, bp.x);
                FFMA2(acc2[i][1], av, bp.y);
            }
        }
        __syncthreads();
    }
#pragma unroll
    for (int i = 0; i < 4; i++) {
        int mm = m0 + ty*4 + i;
        if (mm >= M) continue;
        long rb = (long)mm * N;
        float2 a0 = unpk2(acc2[i][0]);
        float2 a1 = unpk2(acc2[i][1]);
        C[rb + n0 + tx*4 + 0] = a0.x;
        C[rb + n0 + tx*4 + 1] = a0.y;
        C[rb + n0 + tx*4 + 2] = a1.x;
        C[rb + n0 + tx*4 + 3] = a1.y;
    }
}

/* ---------------- BN stats stage 1: partial sums over n-slices ------------------ */
__global__ void bn_stats1_k()
{
    int slice = blockIdx.x, h = blockIdx.y, which = blockIdx.z;
    const float* src = which ? g_k : g_q;
    int n0 = slice * 138;
    int n1 = min(n0 + 138, NQ);
    int cnt = (n1 - n0) * 64;
    double s = 0.0, sq = 0.0;
    for (int i = threadIdx.x; i < cnt; i += 256) {
        int n = n0 + (i >> 6), d = i & 63;
        float v = src[n*KEYD + h*HD + d];
        s += v; sq += (double)v * v;
    }
    __shared__ double rs[256], rq[256];
    rs[threadIdx.x] = s; rq[threadIdx.x] = sq;
    __syncthreads();
    for (int o = 128; o > 0; o >>= 1) {
        if (threadIdx.x < o) { rs[threadIdx.x] += rs[threadIdx.x+o]; rq[threadIdx.x] += rq[threadIdx.x+o]; }
        __syncthreads();
    }
    if (threadIdx.x == 0) {
        int b = (which*HCNT + h)*NSLICE + slice;
        g_part[b*2+0] = rs[0];
        g_part[b*2+1] = rq[0];
    }
}

/* -- BN apply (stats combined inline) + L2 norm -> split bf16 [h][n][192] -------- */
__global__ void bn_apply_k(const float* __restrict__ gamma, const float* __restrict__ beta)
{
    int h = blockIdx.y, which = blockIdx.z;
    double s = 0.0, sq = 0.0;
#pragma unroll
    for (int sl = 0; sl < NSLICE; sl++) {
        int bidx = (which*HCNT + h)*NSLICE + sl;
        s  += g_part[bidx*2+0];
        sq += g_part[bidx*2+1];
    }
    double dmean = s / (double)NHD;
    float mean = (float)dmean;
    float rstd = (float)rsqrt(sq / (double)NHD - dmean*dmean + 1e-5);

    int n = blockIdx.x*4 + (threadIdx.x >> 6);
    int d = threadIdx.x & 63;
    const float* src = which ? g_k : g_q;
    __nv_bfloat16* dst = which ? g_Ks : g_Qs;
    float g = gamma[h], b = beta[h];
    float x = 0.f;
    if (n < NQ) x = (src[n*KEYD + h*HD + d] - mean)*rstd*g + b;
    float sqv = x * x;
#pragma unroll
    for (int o = 16; o > 0; o >>= 1) sqv += __shfl_xor_sync(0xffffffff, sqv, o);
    __shared__ float part[8];
    int w = threadIdx.x >> 5;
    if ((threadIdx.x & 31) == 0) part[w] = sqv;
    __syncthreads();
    int grp = threadIdx.x >> 6;
    float tot = part[grp*2] + part[grp*2+1];
    float y = x / fmaxf(sqrtf(tot), 1e-12f);
    if (n < NQ) {
        __nv_bfloat16 hi = __float2bfloat16(y);
        float rem = y - __bfloat162float(hi);
        __nv_bfloat16 lo = __float2bfloat16(rem);
        long base = ((long)h*NQ + n)*KSPLIT;
        dst[base + d] = hi;
        if (which) {   /* K: [hi | hi | lo] */
            dst[base + 64 + d]  = hi;
            dst[base + 128 + d] = lo;
        } else {       /* Q: [hi | lo | hi] */
            dst[base + 64 + d]  = lo;
            dst[base + 128 + d] = hi;
        }
    }
}

/* --- scores GEMM: 128x64 tile, 8 warps of 32x32, 3-chunk cp.async ring, 3 CTA/SM,
     all 8 heads batched -------------------------------------------------------- */
__global__ void __launch_bounds__(256, 3) score_mma_k(float alpha)
{
    int h = blockIdx.z;
    const __nv_bfloat16* __restrict__ A = g_Ks + (long)h * NQ * KSPLIT;  /* m rows */
    const __nv_bfloat16* __restrict__ B = g_Qs + (long)h * NQ * KSPLIT;  /* q rows */
    float* __restrict__ C = g_scores + (long)h * NQ * NQP;

    extern __shared__ __nv_bfloat16 smemb[];
    __nv_bfloat16* bufA[2] = { smemb, smemb + 128*SPAD3 };
    __nv_bfloat16* bufB[2] = { smemb + 2*128*SPAD3, smemb + 2*128*SPAD3 + 64*SPAD3 };

    int tid = threadIdx.x;
    int m0 = blockIdx.x * 128, n0 = blockIdx.y * 64;

    auto issue_chunk = [&](int c, int s) {
#pragma unroll
        for (int i = 0; i < 6; i++) {
            int idx = tid + i*256;
            int t = idx >= 1024;
            int j = idx - t*1024;
            int row = j >> 3, ch = j & 7;
            int grow = (t ? n0 : m0) + row;
            const __nv_bfloat16* src =
                (t ? B : A) + (long)min(grow, NQ-1)*KSPLIT + c*KC3 + ch*8;
            uint32_t dst = (uint32_t)__cvta_generic_to_shared(
                (t ? bufB[s] : bufA[s]) + row*SPAD3 + ch*8);
            int sz = (grow < NQ) ? 16 : 0;
            CP_ASYNC16(dst, src, sz);
        }
        CP_COMMIT();
    };

    issue_chunk(0, 0);
    issue_chunk(1, 1);

    int wid = tid >> 5, lane = tid & 31;
    int wm = (wid & 3) * 32, wn = (wid >> 2) * 32;   /* 8 warps: 4x2 of 32x32 */
    int sub = lane >> 3, lr = lane & 7;

    float acc[2][4][4];
#pragma unroll
    for (int i = 0; i < 2; i++)
#pragma unroll
        for (int j = 0; j < 4; j++)
#pragma unroll
            for (int v = 0; v < 4; v++) acc[i][j][v] = 0.f;

    auto compute_chunk = [&](int s) {
        __nv_bfloat16* sA = bufA[s];
        __nv_bfloat16* sB = bufB[s];
#pragma unroll
        for (int kt = 0; kt < 4; kt++) {
            int k0 = kt * 16;
            uint32_t a[2][4];
            uint32_t b[4][2];
#pragma unroll
            for (int mi = 0; mi < 2; mi++) {
                int row = wm + mi*16 + (sub & 1)*8 + lr;
                int col = k0 + (sub >> 1)*8;
                uint32_t ad = (uint32_t)__cvta_generic_to_shared(sA + row*SPAD3 + col);
                asm volatile("ldmatrix.sync.aligned.m8n8.x4.shared.b16 {%0,%1,%2,%3}, [%4];"
                    : "=r"(a[mi][0]), "=r"(a[mi][1]), "=r"(a[mi][2]), "=r"(a[mi][3]) : "r"(ad));
            }
#pragma unroll
            for (int nt = 0; nt < 2; nt++) {
                int row = wn + nt*16 + (sub >> 1)*8 + lr;
                int col = k0 + (sub & 1)*8;
                uint32_t ad = (uint32_t)__cvta_generic_to_shared(sB + row*SPAD3 + col);
                uint32_t r0, r1, r2, r3;
                asm volatile("ldmatrix.sync.aligned.m8n8.x4.shared.b16 {%0,%1,%2,%3}, [%4];"
                    : "=r"(r0), "=r"(r1), "=r"(r2), "=r"(r3) : "r"(ad));
                b[nt*2+0][0] = r0; b[nt*2+0][1] = r1;
                b[nt*2+1][0] = r2; b[nt*2+1][1] = r3;
            }
#pragma unroll
            for (int mi = 0; mi < 2; mi++)
#pragma unroll
                for (int nj = 0; nj < 4; nj++) {
                    asm volatile(
                        "mma.sync.aligned.m16n8k16.row.col.f32.bf16.bf16.f32 "
                        "{%0,%1,%2,%3}, {%4,%5,%6,%7}, {%8,%9}, {%0,%1,%2,%3};"
                        : "+f"(acc[mi][nj][0]), "+f"(acc[mi][nj][1]),
                          "+f"(acc[mi][nj][2]), "+f"(acc[mi][nj][3])
                        : "r"(a[mi][0]), "r"(a[mi][1]), "r"(a[mi][2]), "r"(a[mi][3]),
                          "r"(b[nj][0]), "r"(b[nj][1]));
                }
        }
    };

    CP_WAIT(1);
    __syncthreads();
    compute_chunk(0);
    __syncthreads();
    issue_chunk(2, 0);
    CP_WAIT(1);
    __syncthreads();
    compute_chunk(1);
    CP_WAIT(0);
    __syncthreads();
    compute_chunk(0);

    /* epilogue: paired float2 stores (row base 8B-aligned thanks to NQP, q even) */
    int g = lane >> 2, t = lane & 3;
#pragma unroll
    for (int mi = 0; mi < 2; mi++) {
#pragma unroll
        for (int nj = 0; nj < 4; nj++) {
            int m = m0 + wm + mi*16 + g;
            int q = n0 + wn + nj*8 + t*2;
            if (m < NQ && q < NQ) {
                float* p = &C[(long)m*NQP + q];
                if (q + 1 < NQ) *(float2*)p = make_float2(alpha*acc[mi][nj][0], alpha*acc[mi][nj][1]);
                else            *p = alpha*acc[mi][nj][0];
            }
            if (m + 8 < NQ && q < NQ) {
                float* p = &C[(long)(m+8)*NQP + q];
                if (q + 1 < NQ) *(float2*)p = make_float2(alpha*acc[mi][nj][2], alpha*acc[mi][nj][3]);
                else            *p = alpha*acc[mi][nj][2];
            }
        }
    }
}

/* ----- sparsemax tau (Michelot): parity-buffered, 1 barrier/iter, batched ------- */
__global__ void sparsemax_tau_k()
{
    int rowid = blockIdx.x;                     /* [0, HCNT*NQ) */
    long base = (long)rowid * NQP;
    int tid = threadIdx.x;
    float z[9];
    {
        float4 a = *(const float4*)&g_scores[base + tid*4];
        float4 b = *(const float4*)&g_scores[base + 1024 + tid*4];
        z[0]=a.x; z[1]=a.y; z[2]=a.z; z[3]=a.w;
        z[4]=b.x; z[5]=b.y; z[6]=b.z; z[7]=b.w;
        z[8] = (tid < NQ - 2048) ? g_scores[base + 2048 + tid] : -3.4e38f;
    }
    __shared__ float shs[2][8];
    __shared__ int   shc[2][8];
    int lane = tid & 31, w = tid >> 5;

    float s = 0.f;
#pragma unroll
    for (int j = 0; j < 9; j++) if (z[j] > -3.0e38f) s += z[j];
#pragma unroll
    for (int o = 16; o > 0; o >>= 1) s += __shfl_xor_sync(0xffffffff, s, o);
    if (lane == 0) shs[1][w] = s;
    __syncthreads();
    float tot = 0.f;
#pragma unroll
    for (int k = 0; k < 8; k++) tot += shs[1][k];
    float tau = (tot - 1.f) / (float)NQ;

    int cprev = NQ;
    for (int it = 0; it < 64; it++) {
        int p = it & 1;
        float ls = 0.f; int lc = 0;
#pragma unroll
        for (int j = 0; j < 9; j++) {
            float v = z[j];
            if (v > tau) { ls += v; lc++; }
        }
#pragma unroll
        for (int o = 16; o > 0; o >>= 1) {
            ls += __shfl_xor_sync(0xffffffff, ls, o);
            lc += __shfl_xor_sync(0xffffffff, lc, o);
        }
        if (lane == 0) { shs[p][w] = ls; shc[p][w] = lc; }
        __syncthreads();
        float ssum = 0.f; int c = 0;
#pragma unroll
        for (int k = 0; k < 8; k++) { ssum += shs[p][k]; c += shc[p][k]; }
        if (c == 0) break;
        tau = (ssum - 1.f) / (float)c;
        if (c == cprev) break;
        cprev = c;
    }
    if (tid == 0) g_tau[rowid] = tau;
}

/* ----- transpose + relu(z-tau): 64x64 tiles, float4 reads, all heads batched ---- */
__global__ void __launch_bounds__(256) att_transpose_k(float* __restrict__ dst)
{
    __shared__ float tile[64][65];
    __shared__ float stau[64];
    int h = blockIdx.z;
    int m0 = blockIdx.x * 64, q0 = blockIdx.y * 64;
    int tid = threadIdx.x;
    int tx = tid & 15, ty = tid >> 4;
    if (tid < 64) stau[tid] = (m0 + tid < NQ) ? g_tau[h*NQ + m0 + tid] : 0.f;
    __syncthreads();

    if (m0 + 64 <= NQ && q0 + 64 <= NQ) {
#pragma unroll
        for (int i = 0; i < 4; i++) {
            int mr = ty + 16*i;
            float4 v = *(const float4*)&g_scores[((long)(h*NQ + m0 + mr))*NQP + q0 + tx*4];
            float tu = stau[mr];
            tile[mr][tx*4+0] = fmaxf(v.x - tu, 0.f);
            tile[mr][tx*4+1] = fmaxf(v.y - tu, 0.f);
            tile[mr][tx*4+2] = fmaxf(v.z - tu, 0.f);
            tile[mr][tx*4+3] = fmaxf(v.w - tu, 0.f);
        }
        __syncthreads();
#pragma unroll
        for (int i = 0; i < 4; i++) {
            int qr = ty + 16*i;
            long rb = ((long)(8*(q0+qr) + h))*NQ + m0 + tx*4;
            dst[rb+0] = tile[tx*4+0][qr];
            dst[rb+1] = tile[tx*4+1][qr];
            dst[rb+2] = tile[tx*4+2][qr];
            dst[rb+3] = tile[tx*4+3][qr];
        }
    } else {
#pragma unroll 1
        for (int i = 0; i < 16; i++) {
            int mr = ty + 16*(i & 3), qc = tx + 16*(i >> 2);
            int m = m0 + mr, q = q0 + qc;
            if (m < NQ && q < NQ)
                tile[mr][qc] = fmaxf(g_scores[((long)(h*NQ + m))*NQP + q] - stau[mr], 0.f);
        }
        __syncthreads();
#pragma unroll 1
        for (int i = 0; i < 16; i++) {
            int qr = ty + 16*(i & 3), mc = tx + 16*(i >> 2);
            int q = q0 + qr, m = m0 + mc;
            if (m < NQ && q < NQ)
                dst[((long)(8*q + h))*NQ + m] = tile[mc][qr];
        }
    }
}

/* ---- TCL mode-1 (R13-proven): 192 thr, transposed W1 in smem, f32x2 FMA -------- */
__global__ void __launch_bounds__(192) tcl1_k(const float* __restrict__ W1,
                                              const float* __restrict__ att)
{
    extern __shared__ __align__(16) float sWT[];  /* [338][WPAD] = 59488 B */
    for (int j = threadIdx.x; j < LD*FXD; j += 192) {
        int i = j / FXD, a = j - i*FXD;
        sWT[a*WPAD + i] = W1[j];
    }
    for (int j = threadIdx.x; j < FXD*2; j += 192) {
        sWT[(j >> 1)*WPAD + LD + (j & 1)] = 0.f;
    }
    __syncthreads();

    int h2 = blockIdx.x / 13, i2 = blockIdx.x - h2*13;
    int h3 = blockIdx.y / 13, i3 = blockIdx.y - h3*13;
    int tid = threadIdx.x;                      /* 0..191, valid < 169 */
    bool valid = tid < 169;
    int ct = valid ? tid : 0;
    int col = (h2*169 + i2*13 + ct/13)*FXD + h3*169 + i3*13 + (ct - (ct/13)*13);
    int tLow = (h2*2 + h3)*NQ + i2*13 + i3;

    unsigned long long acc2[22];
#pragma unroll
    for (int i = 0; i < 22; i++) acc2[i] = 0ull;

#pragma unroll 1
    for (int h1 = 0; h1 < 2; h1++) {
#pragma unroll 2
        for (int i1 = 0; i1 < 13; i1++) {
            long rowBase = (long)(tLow + h1*4*NQ + i1*169) * NQ + tid;
            int abase = h1*169 + i1*13;
#pragma unroll
            for (int i4 = 0; i4 < 13; i4++) {
                float x = valid ? att[rowBase + i4*169] : 0.f;
                unsigned long long x2 = dup2(x);
                const ulonglong2* w2 = (const ulonglong2*)&sWT[(abase + i4)*WPAD];
#pragma unroll
                for (int v = 0; v < 11; v++) {
                    ulonglong2 p = w2[v];
                    FFMA2(acc2[2*v+0], x2, p.x);
                    FFMA2(acc2[2*v+1], x2, p.y);
                }
            }
        }
    }
    if (valid) {
#pragma unroll
        for (int v = 0; v < 21; v++) {
            float2 f = unpk2(acc2[v]);
            g_out1[(long)(2*v+0)*FX2 + col] = f.x;
            g_out1[(long)(2*v+1)*FX2 + col] = f.y;
        }
    }
}

/* ----- TCL mode-2: b-split halves (grid z), transposed W2 in smem, f32x2 FMA ---- */
__global__ void __launch_bounds__(128) tcl2_k(const float* __restrict__ W2)
{
    extern __shared__ __align__(16) float sWT[];  /* [169][WPAD] = 29744 B */
    int bz = blockIdx.z;
    for (int j = threadIdx.x; j < LD*BHALF; j += 128) {
        int i = j / BHALF, b = j - i*BHALF;
        sWT[b*WPAD + i] = W2[i*FXD + bz*BHALF + b];
    }
    for (int j = threadIdx.x; j < BHALF*2; j += 128) {
        sWT[(j >> 1)*WPAD + LD + (j & 1)] = 0.f;
    }
    __syncthreads();
    int i = blockIdx.y;
    int c = blockIdx.x*128 + threadIdx.x;
    bool valid = c < FXD;
    unsigned long long acc2[22];
#pragma unroll
    for (int j = 0; j < 22; j++) acc2[j] = 0ull;
#pragma unroll 1
    for (int b = 0; b < BHALF; b++) {
        float x = valid ? g_out1[(long)i*FX2 + (bz*BHALF + b)*FXD + c] : 0.f;
        unsigned long long x2 = dup2(x);
        const ulonglong2* w2 = (const ulonglong2*)&sWT[b*WPAD];
#pragma unroll
        for (int v = 0; v < 11; v++) {
            ulonglong2 p = w2[v];
            FFMA2(acc2[2*v+0], x2, p.x);
            FFMA2(acc2[2*v+1], x2, p.y);
        }
    }
    if (valid) {
#pragma unroll
        for (int v = 0; v < 21; v++) {
            float2 f = unpk2(acc2[v]);
            g_out2[bz][(i*LD + 2*v+0)*FXD + c] = f.x;
            g_out2[bz][(i*LD + 2*v+1)*FXD + c] = f.y;
        }
    }
}

/* ---------------- TCL mode-3 + tanh: warp per (i,j) row, sums b-halves ---------- */
__global__ void tcl3_k(const float* __restrict__ W3, float* __restrict__ outp)
{
    extern __shared__ float sW[];               /* 42*338 floats */
    for (int t = threadIdx.x; t < LD*FXD; t += 256) sW[t] = W3[t];
    __syncthreads();
    int w = threadIdx.x >> 5, lane = threadIdx.x & 31;
    int ij = blockIdx.x * 8 + w;
    if (ij >= LD*LD) return;

    float rc[11];
#pragma unroll
    for (int j = 0; j < 11; j++) {
        int c = lane + 32*j;
        rc[j] = (c < FXD) ? (g_out2[0][(long)ij*FXD + c] + g_out2[1][(long)ij*FXD + c]) : 0.f;
    }
#pragma unroll 1
    for (int k = 0; k < LD; k++) {
        const float* wr = sW + k*FXD;
        float s = 0.f;
#pragma unroll
        for (int j = 0; j < 11; j++) {
            int c = lane + 32*j;
            if (c < FXD) s += wr[c] * rc[j];
        }
#pragma unroll
        for (int o = 16; o > 0; o >>= 1) s += __shfl_xor_sync(0xffffffff, s, o);
        if (lane == 0) outp[ij*LD + k] = tanhf(s);
    }
}

/* ================================ host side ==================================== */
extern "C" void kernel_launch(void* const* d_in, const int* in_sizes, int n_in,
                              void* d_out, int out_size)
{
    const float* patches = (const float*)d_in[0];
    const float* Wq    = (const float*)d_in[1];
    const float* Wk    = (const float*)d_in[2];
    const float* gamma = (const float*)d_in[3];
    const float* beta  = (const float*)d_in[4];
    const float* W1    = (const float*)d_in[5];
    const float* W2    = (const float*)d_in[6];
    const float* W3    = (const float*)d_in[7];
    float* outp = (float*)d_out;
    (void)in_sizes; (void)n_in;

    float *pq, *pk, *pAttFallback;
    cudaGetSymbolAddress((void**)&pq,  g_q);
    cudaGetSymbolAddress((void**)&pk,  g_k);
    cudaGetSymbolAddress((void**)&pAttFallback, g_att);

    float* tanh_dest = nullptr;
    float* att_dest  = nullptr;
    if (out_size >= OUT3 + X4TOT)      { tanh_dest = outp; att_dest = outp + OUT3; }
    else if (out_size == X4TOT)        { att_dest = outp; }
    else                               { tanh_dest = outp; att_dest = pAttFallback; }

    const int smW  = FXD*WPAD*4;                /* 59488 */
    const int smW2 = BHALF*WPAD*4;              /* 29744 */
    const int smS  = (2*128 + 2*64)*SPAD3*2;    /* 55296 */
    cudaFuncSetAttribute(score_mma_k, cudaFuncAttributeMaxDynamicSharedMemorySize, smS + 1024);
    cudaFuncSetAttribute(tcl1_k, cudaFuncAttributeMaxDynamicSharedMemorySize, smW + 256);
    cudaFuncSetAttribute(tcl2_k, cudaFuncAttributeMaxDynamicSharedMemorySize, smW2 + 256);
    cudaFuncSetAttribute(tcl3_k, cudaFuncAttributeMaxDynamicSharedMemorySize, LD*FXD*4 + 256);

    const float inv_sqrt_dim = 0.06804138174397717f;  /* 1/sqrt(216) */

    /* 1: q/k projections (batched over z) */
    proj_gemm_k<<<dim3((NQ+63)/64, KEYD/64, 2), 256>>>(patches, Wq, Wk, pq, pk);
    /* 2: BN stats stage 1 */
    bn_stats1_k<<<dim3(NSLICE, HCNT, 2), 256>>>();
    /* 3: BN apply (stats combine inline) + l2 norm -> split bf16 */
    bn_apply_k<<<dim3((NQ + 3)/4, HCNT, 2), 256>>>(gamma, beta);

    /* 4-6: fully batched attention chain (3 launches) */
    score_mma_k<<<dim3((NQ+127)/128, (NQ+63)/64, HCNT), 256, smS>>>(inv_sqrt_dim);
    sparsemax_tau_k<<<HCNT*NQ, 256>>>();
    att_transpose_k<<<dim3((NQ+63)/64, (NQ+63)/64, HCNT), 256>>>(att_dest);

    if (tanh_dest) {
        /* 7: TCL mode-1 (R13-proven 192-thread version) */
        tcl1_k<<<dim3(26, 26), 192, smW>>>(W1, att_dest);
        /* 8: TCL mode-2: b-split halves */
        tcl2_k<<<dim3((FXD + 127)/128, LD, 2), 128, smW2>>>(W2);
        /* 9: TCL mode-3 + tanh */
        tcl3_k<<<(LD*LD + 7)/8, 256, LD*FXD*4>>>(W3, tanh_dest);
    }
}

// round 17
// speedup vs baseline: 1.2808x; 1.2808x over previous
#include <cuda_runtime.h>
#include <cuda_bf16.h>
#include <math.h>
#include <stdint.h>

#define NQ   2197
#define NQP  2200           /* padded scores row stride (16B-aligned rows) */
#define CDIM 216
#define KEYD 512
#define HCNT 8
#define HD   64
#define NHD  (NQ*HD)        /* 140608 */
#define FXD  338
#define FX2  114244         /* 338*338 */
#define LD   42
#define X4TOT 38614472      /* 338^3 == 8*2197^2 */
#define OUT3 74088          /* 42^3 */
#define KSPLIT 192          /* K:[hi|hi|lo]  Q:[hi|lo|hi] -> hh + h*lo + lo*h */
#define KC3  64             /* cp.async K-chunk (3 chunks) */
#define SPAD3 72            /* smem row stride (bf16) for 64-wide chunk */
#define WPAD 44             /* padded i-dim for transposed weights */
#define NSLICE 16           /* bn_stats stage-1 slices */

/* ---------------- packed fp32x2 helpers (Blackwell FFMA2 path) ------------------ */
#define FFMA2(d, a, b) asm("fma.rn.f32x2 %0, %1, %2, %0;" : "+l"(d) : "l"(a), "l"(b))
__device__ __forceinline__ unsigned long long dup2(float x) {
    unsigned long long r;
    asm("mov.b64 %0, {%1, %1};" : "=l"(r) : "f"(x));
    return r;
}
__device__ __forceinline__ float2 unpk2(unsigned long long d) {
    float2 f;
    asm("mov.b64 {%0, %1}, %2;" : "=f"(f.x), "=f"(f.y) : "l"(d));
    return f;
}
#define CP_ASYNC16(dst, src, sz) \
    asm volatile("cp.async.cg.shared.global [%0], [%1], 16, %2;" :: "r"(dst), "l"(src), "r"(sz))
#define CP_COMMIT() asm volatile("cp.async.commit_group;" ::: "memory")
#define CP_WAIT(n)  asm volatile("cp.async.wait_group %0;" :: "n"(n) : "memory")

/* ---------------- static device scratch (no runtime allocation) ---------------- */
__device__ float g_q[NQ*KEYD];
__device__ float g_k[NQ*KEYD];
__device__ __nv_bfloat16 g_Qs[(long)HCNT*NQ*KSPLIT];
__device__ __nv_bfloat16 g_Ks[(long)HCNT*NQ*KSPLIT];
__device__ double g_part[2*HCNT*NSLICE*2];
__device__ float g_stats[2*HCNT*2];
__device__ float g_scores[(long)HCNT*NQ*NQP]; /* scoresT[h][m][q], stride NQP */
__device__ float g_tau[HCNT*NQ];
__device__ float g_att[(long)X4TOT];          /* fallback att(t,m) dest */
__device__ float g_out1[(long)LD*FX2];
__device__ float g_out2[LD*LD*FXD];

/* ------- fp32 projection GEMM: 64x64 tile, 4x4/thread, f32x2 FMA, K=216 -------- */
__global__ void proj_gemm_k(const float* __restrict__ A,
                            const float* __restrict__ B0, const float* __restrict__ B1,
                            float* __restrict__ C0, float* __restrict__ C1)
{
    const float* __restrict__ B = blockIdx.z ? B1 : B0;
    float* __restrict__ C = blockIdx.z ? C1 : C0;
    const int M = NQ, N = KEYD, K = CDIM;

    __shared__ float As[32][65];
    __shared__ __align__(16) float Bs[32][68];

    int tid = threadIdx.x;
    int tx = tid & 15, ty = tid >> 4;
    int m0 = blockIdx.x * 64, n0 = blockIdx.y * 64;
    unsigned long long acc2[4][2];
#pragma unroll
    for (int i = 0; i < 4; i++) { acc2[i][0] = 0ull; acc2[i][1] = 0ull; }

    for (int k0 = 0; k0 < K; k0 += 32) {
#pragma unroll
        for (int l = 0; l < 2; l++) {
            int s = tid + l * 256;
            int row = s >> 3, kq = s & 7;
            bool kok = (k0 + kq*4) < K;
            int mm = m0 + row;
            float4 va = make_float4(0.f,0.f,0.f,0.f);
            if (mm < M && kok) va = *(const float4*)&A[(long)mm * K + k0 + kq*4];
            As[kq*4+0][row] = va.x; As[kq*4+1][row] = va.y;
            As[kq*4+2][row] = va.z; As[kq*4+3][row] = va.w;
            int nn = n0 + row;
            float4 vb = make_float4(0.f,0.f,0.f,0.f);
            if (kok) vb = *(const float4*)&B[(long)nn * K + k0 + kq*4];
            Bs[kq*4+0][row] = vb.x; Bs[kq*4+1][row] = vb.y;
            Bs[kq*4+2][row] = vb.z; Bs[kq*4+3][row] = vb.w;
        }
        __syncthreads();
#pragma unroll
        for (int k = 0; k < 32; k++) {
            ulonglong2 bp = *(const ulonglong2*)&Bs[k][tx*4];
#pragma unroll
            for (int i = 0; i < 4; i++) {
                unsigned long long av = dup2(As[k][ty*4+i]);
                FFMA2(acc2[i][0], av, bp.x);
                FFMA2(acc2[i][1], av, bp.y);
            }
        }
        __syncthreads();
    }
#pragma unroll
    for (int i = 0; i < 4; i++) {
        int mm = m0 + ty*4 + i;
        if (mm >= M) continue;
        long rb = (long)mm * N;
        float2 a0 = unpk2(acc2[i][0]);
        float2 a1 = unpk2(acc2[i][1]);
        C[rb + n0 + tx*4 + 0] = a0.x;
        C[rb + n0 + tx*4 + 1] = a0.y;
        C[rb + n0 + tx*4 + 2] = a1.x;
        C[rb + n0 + tx*4 + 3] = a1.y;
    }
}

/* ---------------- BN stats stage 1: partial sums over n-slices ------------------ */
__global__ void bn_stats1_k()
{
    int slice = blockIdx.x, h = blockIdx.y, which = blockIdx.z;
    const float* src = which ? g_k : g_q;
    int n0 = slice * 138;
    int n1 = min(n0 + 138, NQ);
    int cnt = (n1 - n0) * 64;
    double s = 0.0, sq = 0.0;
    for (int i = threadIdx.x; i < cnt; i += 256) {
        int n = n0 + (i >> 6), d = i & 63;
        float v = src[n*KEYD + h*HD + d];
        s += v; sq += (double)v * v;
    }
    __shared__ double rs[256], rq[256];
    rs[threadIdx.x] = s; rq[threadIdx.x] = sq;
    __syncthreads();
    for (int o = 128; o > 0; o >>= 1) {
        if (threadIdx.x < o) { rs[threadIdx.x] += rs[threadIdx.x+o]; rq[threadIdx.x] += rq[threadIdx.x+o]; }
        __syncthreads();
    }
    if (threadIdx.x == 0) {
        int b = (which*HCNT + h)*NSLICE + slice;
        g_part[b*2+0] = rs[0];
        g_part[b*2+1] = rq[0];
    }
}

/* ---------------- BN stats stage 2: combine ------------------------------------- */
__global__ void bn_stats2_k()
{
    int h = blockIdx.x, which = blockIdx.y;
    int lane = threadIdx.x;
    double s = 0.0, sq = 0.0;
    if (lane < NSLICE) {
        int b = (which*HCNT + h)*NSLICE + lane;
        s = g_part[b*2+0]; sq = g_part[b*2+1];
    }
#pragma unroll
    for (int o = 8; o > 0; o >>= 1) {
        s  += __shfl_xor_sync(0xffffffff, s,  o);
        sq += __shfl_xor_sync(0xffffffff, sq, o);
    }
    if (lane == 0) {
        double mean = s / (double)NHD;
        double var  = sq / (double)NHD - mean*mean;
        g_stats[(which*HCNT + h)*2 + 0] = (float)mean;
        g_stats[(which*HCNT + h)*2 + 1] = (float)rsqrt(var + 1e-5);
    }
}

/* -- BN apply + L2 norm -> split bf16 [h][n][192]; K:[hi|hi|lo]  Q:[hi|lo|hi] --- */
__global__ void bn_apply_k(const float* __restrict__ gamma, const float* __restrict__ beta)
{
    int h = blockIdx.y, which = blockIdx.z;
    int n = blockIdx.x*4 + (threadIdx.x >> 6);
    int d = threadIdx.x & 63;
    const float* src = which ? g_k : g_q;
    __nv_bfloat16* dst = which ? g_Ks : g_Qs;
    float mean = g_stats[(which*HCNT+h)*2];
    float rstd = g_stats[(which*HCNT+h)*2+1];
    float g = gamma[h], b = beta[h];
    float x = 0.f;
    if (n < NQ) x = (src[n*KEYD + h*HD + d] - mean)*rstd*g + b;
    float sq = x * x;
#pragma unroll
    for (int o = 16; o > 0; o >>= 1) sq += __shfl_xor_sync(0xffffffff, sq, o);
    __shared__ float part[8];
    int w = threadIdx.x >> 5;
    if ((threadIdx.x & 31) == 0) part[w] = sq;
    __syncthreads();
    int grp = threadIdx.x >> 6;
    float tot = part[grp*2] + part[grp*2+1];
    float y = x / fmaxf(sqrtf(tot), 1e-12f);
    if (n < NQ) {
        __nv_bfloat16 hi = __float2bfloat16(y);
        float rem = y - __bfloat162float(hi);
        __nv_bfloat16 lo = __float2bfloat16(rem);
        long base = ((long)h*NQ + n)*KSPLIT;
        dst[base + d] = hi;
        if (which) {   /* K: [hi | hi | lo] */
            dst[base + 64 + d]  = hi;
            dst[base + 128 + d] = lo;
        } else {       /* Q: [hi | lo | hi] */
            dst[base + 64 + d]  = lo;
            dst[base + 128 + d] = hi;
        }
    }
}

/* --- scores GEMM: 128x64 tile, 8 warps of 32x32, 3-chunk cp.async ring, 3 CTA/SM,
     all 8 heads batched -------------------------------------------------------- */
__global__ void __launch_bounds__(256, 3) score_mma_k(float alpha)
{
    int h = blockIdx.z;
    const __nv_bfloat16* __restrict__ A = g_Ks + (long)h * NQ * KSPLIT;  /* m rows */
    const __nv_bfloat16* __restrict__ B = g_Qs + (long)h * NQ * KSPLIT;  /* q rows */
    float* __restrict__ C = g_scores + (long)h * NQ * NQP;

    extern __shared__ __nv_bfloat16 smemb[];
    __nv_bfloat16* bufA[2] = { smemb, smemb + 128*SPAD3 };
    __nv_bfloat16* bufB[2] = { smemb + 2*128*SPAD3, smemb + 2*128*SPAD3 + 64*SPAD3 };

    int tid = threadIdx.x;
    int m0 = blockIdx.x * 128, n0 = blockIdx.y * 64;

    auto issue_chunk = [&](int c, int s) {
#pragma unroll
        for (int i = 0; i < 6; i++) {
            int idx = tid + i*256;
            int t = idx >= 1024;
            int j = idx - t*1024;
            int row = j >> 3, ch = j & 7;
            int grow = (t ? n0 : m0) + row;
            const __nv_bfloat16* src =
                (t ? B : A) + (long)min(grow, NQ-1)*KSPLIT + c*KC3 + ch*8;
            uint32_t dst = (uint32_t)__cvta_generic_to_shared(
                (t ? bufB[s] : bufA[s]) + row*SPAD3 + ch*8);
            int sz = (grow < NQ) ? 16 : 0;
            CP_ASYNC16(dst, src, sz);
        }
        CP_COMMIT();
    };

    issue_chunk(0, 0);
    issue_chunk(1, 1);

    int wid = tid >> 5, lane = tid & 31;
    int wm = (wid & 3) * 32, wn = (wid >> 2) * 32;   /* 8 warps: 4x2 of 32x32 */
    int sub = lane >> 3, lr = lane & 7;

    float acc[2][4][4];
#pragma unroll
    for (int i = 0; i < 2; i++)
#pragma unroll
        for (int j = 0; j < 4; j++)
#pragma unroll
            for (int v = 0; v < 4; v++) acc[i][j][v] = 0.f;

    auto compute_chunk = [&](int s) {
        __nv_bfloat16* sA = bufA[s];
        __nv_bfloat16* sB = bufB[s];
#pragma unroll
        for (int kt = 0; kt < 4; kt++) {
            int k0 = kt * 16;
            uint32_t a[2][4];
            uint32_t b[4][2];
#pragma unroll
            for (int mi = 0; mi < 2; mi++) {
                int row = wm + mi*16 + (sub & 1)*8 + lr;
                int col = k0 + (sub >> 1)*8;
                uint32_t ad = (uint32_t)__cvta_generic_to_shared(sA + row*SPAD3 + col);
                asm volatile("ldmatrix.sync.aligned.m8n8.x4.shared.b16 {%0,%1,%2,%3}, [%4];"
                    : "=r"(a[mi][0]), "=r"(a[mi][1]), "=r"(a[mi][2]), "=r"(a[mi][3]) : "r"(ad));
            }
#pragma unroll
            for (int nt = 0; nt < 2; nt++) {
                int row = wn + nt*16 + (sub >> 1)*8 + lr;
                int col = k0 + (sub & 1)*8;
                uint32_t ad = (uint32_t)__cvta_generic_to_shared(sB + row*SPAD3 + col);
                uint32_t r0, r1, r2, r3;
                asm volatile("ldmatrix.sync.aligned.m8n8.x4.shared.b16 {%0,%1,%2,%3}, [%4];"
                    : "=r"(r0), "=r"(r1), "=r"(r2), "=r"(r3) : "r"(ad));
                b[nt*2+0][0] = r0; b[nt*2+0][1] = r1;
                b[nt*2+1][0] = r2; b[nt*2+1][1] = r3;
            }
#pragma unroll
            for (int mi = 0; mi < 2; mi++)
#pragma unroll
                for (int nj = 0; nj < 4; nj++) {
                    asm volatile(
                        "mma.sync.aligned.m16n8k16.row.col.f32.bf16.bf16.f32 "
                        "{%0,%1,%2,%3}, {%4,%5,%6,%7}, {%8,%9}, {%0,%1,%2,%3};"
                        : "+f"(acc[mi][nj][0]), "+f"(acc[mi][nj][1]),
                          "+f"(acc[mi][nj][2]), "+f"(acc[mi][nj][3])
                        : "r"(a[mi][0]), "r"(a[mi][1]), "r"(a[mi][2]), "r"(a[mi][3]),
                          "r"(b[nj][0]), "r"(b[nj][1]));
                }
        }
    };

    CP_WAIT(1);
    __syncthreads();
    compute_chunk(0);
    __syncthreads();
    issue_chunk(2, 0);
    CP_WAIT(1);
    __syncthreads();
    compute_chunk(1);
    CP_WAIT(0);
    __syncthreads();
    compute_chunk(0);

    /* epilogue: paired float2 stores (row base 8B-aligned thanks to NQP, q even) */
    int g = lane >> 2, t = lane & 3;
#pragma unroll
    for (int mi = 0; mi < 2; mi++) {
#pragma unroll
        for (int nj = 0; nj < 4; nj++) {
            int m = m0 + wm + mi*16 + g;
            int q = n0 + wn + nj*8 + t*2;
            if (m < NQ && q < NQ) {
                float* p = &C[(long)m*NQP + q];
                if (q + 1 < NQ) *(float2*)p = make_float2(alpha*acc[mi][nj][0], alpha*acc[mi][nj][1]);
                else            *p = alpha*acc[mi][nj][0];
            }
            if (m + 8 < NQ && q < NQ) {
                float* p = &C[(long)(m+8)*NQP + q];
                if (q + 1 < NQ) *(float2*)p = make_float2(alpha*acc[mi][nj][2], alpha*acc[mi][nj][3]);
                else            *p = alpha*acc[mi][nj][2];
            }
        }
    }
}

/* ----- sparsemax tau (Michelot): parity-buffered, 1 barrier/iter, batched ------- */
__global__ void sparsemax_tau_k()
{
    int rowid = blockIdx.x;                     /* [0, HCNT*NQ) */
    long base = (long)rowid * NQP;
    int tid = threadIdx.x;
    float z[9];
    {
        float4 a = *(const float4*)&g_scores[base + tid*4];
        float4 b = *(const float4*)&g_scores[base + 1024 + tid*4];
        z[0]=a.x; z[1]=a.y; z[2]=a.z; z[3]=a.w;
        z[4]=b.x; z[5]=b.y; z[6]=b.z; z[7]=b.w;
        z[8] = (tid < NQ - 2048) ? g_scores[base + 2048 + tid] : -3.4e38f;
    }
    __shared__ float shs[2][8];
    __shared__ int   shc[2][8];
    int lane = tid & 31, w = tid >> 5;

    float s = 0.f;
#pragma unroll
    for (int j = 0; j < 9; j++) if (z[j] > -3.0e38f) s += z[j];
#pragma unroll
    for (int o = 16; o > 0; o >>= 1) s += __shfl_xor_sync(0xffffffff, s, o);
    if (lane == 0) shs[1][w] = s;
    __syncthreads();
    float tot = 0.f;
#pragma unroll
    for (int k = 0; k < 8; k++) tot += shs[1][k];
    float tau = (tot - 1.f) / (float)NQ;

    int cprev = NQ;
    for (int it = 0; it < 64; it++) {
        int p = it & 1;
        float ls = 0.f; int lc = 0;
#pragma unroll
        for (int j = 0; j < 9; j++) {
            float v = z[j];
            if (v > tau) { ls += v; lc++; }
        }
#pragma unroll
        for (int o = 16; o > 0; o >>= 1) {
            ls += __shfl_xor_sync(0xffffffff, ls, o);
            lc += __shfl_xor_sync(0xffffffff, lc, o);
        }
        if (lane == 0) { shs[p][w] = ls; shc[p][w] = lc; }
        __syncthreads();
        float ssum = 0.f; int c = 0;
#pragma unroll
        for (int k = 0; k < 8; k++) { ssum += shs[p][k]; c += shc[p][k]; }
        if (c == 0) break;
        tau = (ssum - 1.f) / (float)c;
        if (c == cprev) break;
        cprev = c;
    }
    if (tid == 0) g_tau[rowid] = tau;
}

/* ----- transpose + relu(z-tau): 64x64 tiles, float4 reads, all heads batched ---- */
__global__ void __launch_bounds__(256) att_transpose_k(float* __restrict__ dst)
{
    __shared__ float tile[64][65];
    __shared__ float stau[64];
    int h = blockIdx.z;
    int m0 = blockIdx.x * 64, q0 = blockIdx.y * 64;
    int tid = threadIdx.x;
    int tx = tid & 15, ty = tid >> 4;
    if (tid < 64) stau[tid] = (m0 + tid < NQ) ? g_tau[h*NQ + m0 + tid] : 0.f;
    __syncthreads();

    if (m0 + 64 <= NQ && q0 + 64 <= NQ) {
#pragma unroll
        for (int i = 0; i < 4; i++) {
            int mr = ty + 16*i;
            float4 v = *(const float4*)&g_scores[((long)(h*NQ + m0 + mr))*NQP + q0 + tx*4];
            float tu = stau[mr];
            tile[mr][tx*4+0] = fmaxf(v.x - tu, 0.f);
            tile[mr][tx*4+1] = fmaxf(v.y - tu, 0.f);
            tile[mr][tx*4+2] = fmaxf(v.z - tu, 0.f);
            tile[mr][tx*4+3] = fmaxf(v.w - tu, 0.f);
        }
        __syncthreads();
#pragma unroll
        for (int i = 0; i < 4; i++) {
            int qr = ty + 16*i;
            long rb = ((long)(8*(q0+qr) + h))*NQ + m0 + tx*4;
            dst[rb+0] = tile[tx*4+0][qr];
            dst[rb+1] = tile[tx*4+1][qr];
            dst[rb+2] = tile[tx*4+2][qr];
            dst[rb+3] = tile[tx*4+3][qr];
        }
    } else {
#pragma unroll 1
        for (int i = 0; i < 16; i++) {
            int mr = ty + 16*(i & 3), qc = tx + 16*(i >> 2);
            int m = m0 + mr, q = q0 + qc;
            if (m < NQ && q < NQ)
                tile[mr][qc] = fmaxf(g_scores[((long)(h*NQ + m))*NQP + q] - stau[mr], 0.f);
        }
        __syncthreads();
#pragma unroll 1
        for (int i = 0; i < 16; i++) {
            int qr = ty + 16*(i & 3), mc = tx + 16*(i >> 2);
            int q = q0 + qr, m = m0 + mc;
            if (m < NQ && q < NQ)
                dst[((long)(8*q + h))*NQ + m] = tile[mc][qr];
        }
    }
}

/* ---- TCL mode-1: coalesced att gather, transposed W1 in smem, f32x2 FMA -------- */
__global__ void __launch_bounds__(192) tcl1_k(const float* __restrict__ W1,
                                              const float* __restrict__ att)
{
    extern __shared__ __align__(16) float sWT[];  /* [338][WPAD] = 59488 B */
    for (int j = threadIdx.x; j < LD*FXD; j += 192) {
        int i = j / FXD, a = j - i*FXD;
        sWT[a*WPAD + i] = W1[j];
    }
    for (int j = threadIdx.x; j < FXD*2; j += 192) {
        sWT[(j >> 1)*WPAD + LD + (j & 1)] = 0.f;
    }
    __syncthreads();

    int h2 = blockIdx.x / 13, i2 = blockIdx.x - h2*13;
    int h3 = blockIdx.y / 13, i3 = blockIdx.y - h3*13;
    int tid = threadIdx.x;                      /* 0..191, valid < 169 */
    bool valid = tid < 169;
    int ct = valid ? tid : 0;
    int col = (h2*169 + i2*13 + ct/13)*FXD + h3*169 + i3*13 + (ct - (ct/13)*13);
    int tLow = (h2*2 + h3)*NQ + i2*13 + i3;

    unsigned long long acc2[22];
#pragma unroll
    for (int i = 0; i < 22; i++) acc2[i] = 0ull;

#pragma unroll 1
    for (int h1 = 0; h1 < 2; h1++) {
#pragma unroll 2
        for (int i1 = 0; i1 < 13; i1++) {
            long rowBase = (long)(tLow + h1*4*NQ + i1*169) * NQ + tid;
            int abase = h1*169 + i1*13;
#pragma unroll
            for (int i4 = 0; i4 < 13; i4++) {
                float x = valid ? att[rowBase + i4*169] : 0.f;
                unsigned long long x2 = dup2(x);
                const ulonglong2* w2 = (const ulonglong2*)&sWT[(abase + i4)*WPAD];
#pragma unroll
                for (int v = 0; v < 11; v++) {
                    ulonglong2 p = w2[v];
                    FFMA2(acc2[2*v+0], x2, p.x);
                    FFMA2(acc2[2*v+1], x2, p.y);
                }
            }
        }
    }
    if (valid) {
#pragma unroll
        for (int v = 0; v < 21; v++) {
            float2 f = unpk2(acc2[v]);
            g_out1[(long)(2*v+0)*FX2 + col] = f.x;
            g_out1[(long)(2*v+1)*FX2 + col] = f.y;
        }
    }
}

/* ---------------- TCL mode-2: transposed W2 in smem, f32x2 FMA ------------------ */
__global__ void __launch_bounds__(128) tcl2_k(const float* __restrict__ W2)
{
    extern __shared__ __align__(16) float sWT[];  /* [338][WPAD] */
    for (int j = threadIdx.x; j < LD*FXD; j += 128) {
        int i = j / FXD, b = j - i*FXD;
        sWT[b*WPAD + i] = W2[j];
    }
    for (int j = threadIdx.x; j < FXD*2; j += 128) {
        sWT[(j >> 1)*WPAD + LD + (j & 1)] = 0.f;
    }
    __syncthreads();
    int i = blockIdx.y;
    int c = blockIdx.x*128 + threadIdx.x;
    bool valid = c < FXD;
    unsigned long long acc2[22];
#pragma unroll
    for (int j = 0; j < 22; j++) acc2[j] = 0ull;
#pragma unroll 1
    for (int b = 0; b < FXD; b++) {
        float x = valid ? g_out1[(long)i*FX2 + b*FXD + c] : 0.f;
        unsigned long long x2 = dup2(x);
        const ulonglong2* w2 = (const ulonglong2*)&sWT[b*WPAD];
#pragma unroll
        for (int v = 0; v < 11; v++) {
            ulonglong2 p = w2[v];
            FFMA2(acc2[2*v+0], x2, p.x);
            FFMA2(acc2[2*v+1], x2, p.y);
        }
    }
    if (valid) {
#pragma unroll
        for (int v = 0; v < 21; v++) {
            float2 f = unpk2(acc2[v]);
            g_out2[(i*LD + 2*v+0)*FXD + c] = f.x;
            g_out2[(i*LD + 2*v+1)*FXD + c] = f.y;
        }
    }
}

/* ---------------- TCL mode-3 + tanh: warp per (i,j) row ------------------------- */
__global__ void tcl3_k(const float* __restrict__ W3, float* __restrict__ outp)
{
    extern __shared__ float sW[];               /* 42*338 floats */
    for (int t = threadIdx.x; t < LD*FXD; t += 256) sW[t] = W3[t];
    __syncthreads();
    int w = threadIdx.x >> 5, lane = threadIdx.x & 31;
    int ij = blockIdx.x * 8 + w;
    if (ij >= LD*LD) return;

    float rc[11];
#pragma unroll
    for (int j = 0; j < 11; j++) {
        int c = lane + 32*j;
        rc[j] = (c < FXD) ? g_out2[(long)ij*FXD + c] : 0.f;
    }
#pragma unroll 1
    for (int k = 0; k < LD; k++) {
        const float* wr = sW + k*FXD;
        float s = 0.f;
#pragma unroll
        for (int j = 0; j < 11; j++) {
            int c = lane + 32*j;
            if (c < FXD) s += wr[c] * rc[j];
        }
#pragma unroll
        for (int o = 16; o > 0; o >>= 1) s += __shfl_xor_sync(0xffffffff, s, o);
        if (lane == 0) outp[ij*LD + k] = tanhf(s);
    }
}

/* ================================ host side ==================================== */
extern "C" void kernel_launch(void* const* d_in, const int* in_sizes, int n_in,
                              void* d_out, int out_size)
{
    const float* patches = (const float*)d_in[0];
    const float* Wq    = (const float*)d_in[1];
    const float* Wk    = (const float*)d_in[2];
    const float* gamma = (const float*)d_in[3];
    const float* beta  = (const float*)d_in[4];
    const float* W1    = (const float*)d_in[5];
    const float* W2    = (const float*)d_in[6];
    const float* W3    = (const float*)d_in[7];
    float* outp = (float*)d_out;
    (void)in_sizes; (void)n_in;

    float *pq, *pk, *pAttFallback;
    cudaGetSymbolAddress((void**)&pq,  g_q);
    cudaGetSymbolAddress((void**)&pk,  g_k);
    cudaGetSymbolAddress((void**)&pAttFallback, g_att);

    float* tanh_dest = nullptr;
    float* att_dest  = nullptr;
    if (out_size >= OUT3 + X4TOT)      { tanh_dest = outp; att_dest = outp + OUT3; }
    else if (out_size == X4TOT)        { att_dest = outp; }
    else                               { tanh_dest = outp; att_dest = pAttFallback; }

    const int smW  = FXD*WPAD*4;                /* 59488 */
    const int smS  = (2*128 + 2*64)*SPAD3*2;    /* 55296 */
    cudaFuncSetAttribute(score_mma_k, cudaFuncAttributeMaxDynamicSharedMemorySize, smS + 1024);
    cudaFuncSetAttribute(tcl1_k, cudaFuncAttributeMaxDynamicSharedMemorySize, smW + 256);
    cudaFuncSetAttribute(tcl2_k, cudaFuncAttributeMaxDynamicSharedMemorySize, smW + 256);
    cudaFuncSetAttribute(tcl3_k, cudaFuncAttributeMaxDynamicSharedMemorySize, LD*FXD*4 + 256);

    const float inv_sqrt_dim = 0.06804138174397717f;  /* 1/sqrt(216) */

    /* 1: q/k projections (batched over z) */
    proj_gemm_k<<<dim3((NQ+63)/64, KEYD/64, 2), 256>>>(patches, Wq, Wk, pq, pk);
    /* 2: BN stats, two-stage */
    bn_stats1_k<<<dim3(NSLICE, HCNT, 2), 256>>>();
    bn_stats2_k<<<dim3(HCNT, 2), 32>>>();
    /* 3: BN apply + l2 norm -> split bf16 (K=[hi|hi|lo], Q=[hi|lo|hi]) */
    bn_apply_k<<<dim3((NQ + 3)/4, HCNT, 2), 256>>>(gamma, beta);

    /* 4-6: fully batched attention chain (3 launches) */
    score_mma_k<<<dim3((NQ+127)/128, (NQ+63)/64, HCNT), 256, smS>>>(inv_sqrt_dim);
    sparsemax_tau_k<<<HCNT*NQ, 256>>>();
    att_transpose_k<<<dim3((NQ+63)/64, (NQ+63)/64, HCNT), 256>>>(att_dest);

    if (tanh_dest) {
        /* 7: TCL mode-1, f32x2 packed FMA */
        tcl1_k<<<dim3(26, 26), 192, smW>>>(W1, att_dest);
        /* 8,9: remaining contractions + tanh */
        tcl2_k<<<dim3((FXD + 127)/128, LD), 128, smW>>>(W2);
        tcl3_k<<<(LD*LD + 7)/8, 256, LD*FXD*4>>>(W3, tanh_dest);
    }
}